// round 13
// baseline (speedup 1.0000x reference)
#include <cuda_runtime.h>
#include <cuda_bf16.h>
#include <math.h>

#define DD 64
#define KK 512
#define NV 65536
#define DECAYF 0.99f
#define EPSF 1e-5f

// Output layout (concatenated float32, reference tuple order)
#define OFF_Q      0
#define OFF_LOSS   (NV * DD)
#define OFF_PERP   (OFF_LOSS + 1)
#define OFF_IDX    (OFF_PERP + 1)
#define OFF_NEWEMB (OFF_IDX + NV)
#define OFF_HIDCS  (OFF_NEWEMB + DD*KK)
#define OFF_HIDDW  (OFF_HIDCS + KK)

typedef unsigned long long ull;
typedef unsigned short ushort;

#define KE    384            // 6 segments x 64
#define NSEG  6
#define STRB  784            // smem row stride bytes (392 bf16): conflict-free ldmatrix
#define ROWT  64             // rows per tile
#define NT64  (NV / ROWT)    // 1024 tiles
#define TPB   256
#define GRIDM 148            // 4 quarters x 37 slots

// smem: B' quarter [128][STRB], A' tile [64][STRB], esq [128]
#define SM_B   0
#define SM_A   (128 * STRB)              // 100352
#define SM_ESQ (SM_A + 64 * STRB)        // 150528
#define SMEMM  (SM_ESQ + 512)            // 151040

// ---------- helpers ----------
__device__ __forceinline__ unsigned smem_u32(const void* p) {
    unsigned a;
    asm("{ .reg .u64 t; cvta.to.shared.u64 t, %1; cvt.u32.u64 %0, t; }" : "=r"(a) : "l"(p));
    return a;
}
__device__ __forceinline__ void ldsm_x4(unsigned& r0, unsigned& r1, unsigned& r2, unsigned& r3,
                                        unsigned addr) {
    asm volatile("ldmatrix.sync.aligned.m8n8.x4.shared.b16 {%0,%1,%2,%3}, [%4];"
                 : "=r"(r0), "=r"(r1), "=r"(r2), "=r"(r3) : "r"(addr));
}
__device__ __forceinline__ void mma16816(float* d, const unsigned* a, unsigned b0, unsigned b1) {
    asm volatile("mma.sync.aligned.m16n8k16.row.col.f32.bf16.bf16.f32 "
                 "{%0,%1,%2,%3}, {%4,%5,%6,%7}, {%8,%9}, {%0,%1,%2,%3};"
                 : "+f"(d[0]), "+f"(d[1]), "+f"(d[2]), "+f"(d[3])
                 : "r"(a[0]), "r"(a[1]), "r"(a[2]), "r"(a[3]), "r"(b0), "r"(b1));
}
// Monotonic float->uint key; idx low 32 -> u64 min == (min score, min idx)
__device__ __forceinline__ ull keyf(float s, unsigned idx) {
    unsigned u = __float_as_uint(s);
    u = (u & 0x80000000u) ? ~u : (u | 0x80000000u);
    return ((ull)u << 32) | (ull)idx;
}
__device__ __forceinline__ ull umin64(ull a, ull b) { return a < b ? a : b; }

__device__ __forceinline__ void split3(float v, ushort& a, ushort& b, ushort& c) {
    __nv_bfloat16 h0 = __float2bfloat16(v);
    float r  = v - __bfloat162float(h0);
    __nv_bfloat16 h1 = __float2bfloat16(r);
    float r2 = r - __bfloat162float(h1);
    __nv_bfloat16 h2 = __float2bfloat16(r2);
    a = __bfloat16_as_ushort(h0); b = __bfloat16_as_ushort(h1); c = __bfloat16_as_ushort(h2);
}

// ---------- device scratch (zero-init; consumers restore) ----------
__device__ float  g_dw[DD * KK];
__device__ float  g_cs[KK];
__device__ float  g_loss;
__device__ float  g_inv_stable[KK];
__device__ float  g_inv_debias;
__device__ ull    g_best[NV];             // atomicMax(~key); reset by k_finish
__device__ ushort g_bsplit[KK * KE];      // B' [code][384] bf16 segments
__device__ float4 g_eTv[KK * 16];         // fp32 codebook [code][64]

// ---------- prep: codebook -> fp32 transpose + 6-seg bf16 B' ----------
__global__ void k_prep_e(const float* __restrict__ emb) {
    int gid = blockIdx.x * 512 + threadIdx.x;        // 32768
    int d = gid >> 9, k = gid & 511;
    float v = emb[gid];                               // coalesced
    ((float*)g_eTv)[k * 64 + d] = v;
    ushort a, b, c;
    split3(v, a, b, c);
    ushort* row = g_bsplit + (size_t)k * KE;
    // TB = {0,1,0,1,2,0}: e0 -> segs 0,2,5; e1 -> segs 1,3; e2 -> seg 4
    row[0 * 64 + d] = a; row[2 * 64 + d] = a; row[5 * 64 + d] = a;
    row[1 * 64 + d] = b; row[3 * 64 + d] = b;
    row[4 * 64 + d] = c;
}

// ---------- HMMA argmin: block = quarter of codes, tiles of 64 rows ----------
__global__ void __launch_bounds__(TPB, 1) k_mma(
    const float* __restrict__ x, const float* __restrict__ emb)
{
    extern __shared__ char sm[];
    const unsigned smb = smem_u32(sm);
    const int t = threadIdx.x, w = t >> 5, l = t & 31;
    const int quarter = blockIdx.x & 3, slot = blockIdx.x >> 2;   // 37 slots
    const int qbase = quarter * 128;

    // stage B' quarter: 128 codes x 384 bf16 (row stride STRB in smem)
    for (int i = t; i < 128 * 48; i += TPB) {        // 48 float4 per row
        int code = i / 48, c = i % 48;
        *(float4*)(sm + SM_B + code * STRB + c * 16)
            = *(const float4*)((const char*)g_bsplit + ((size_t)(qbase + code) * KE + c * 8) * 2);
    }
    // exact fp32 ||e||^2 for this quarter
    if (t < 128) {
        float s = 0.0f;
        #pragma unroll 8
        for (int d = 0; d < DD; d++) {
            float v = emb[d * KK + qbase + t];
            s = fmaf(v, v, s);
        }
        ((float*)(sm + SM_ESQ))[t] = s;
    }
    __syncthreads();

    // warp layout: rows 16*(w&3), codes 64*(w>>2) within quarter
    const int aRow = (w & 3) * 16;
    const int cLoc = (w >> 2) * 64;                  // 0 or 64 (local code base)
    const float* esq_s = (const float*)(sm + SM_ESQ);

    const unsigned aAddrBase = smb + SM_A + (aRow + (l & 15)) * STRB + (l >> 4) * 16;

    for (int tile = slot; tile < NT64; tile += 37) {
        // --- build A' for this tile: split x in-kernel into 6 segments ---
        #pragma unroll
        for (int i = 0; i < 4; i++) {
            int c   = t + TPB * i;                   // 0..1023
            int row = c >> 4;
            int dq  = (c & 15) * 4;
            float4 v = *(const float4*)(x + (size_t)(tile * ROWT + row) * DD + dq);
            float f[4] = {v.x, v.y, v.z, v.w};
            ushort a0[4], a1[4], a2[4];
            #pragma unroll
            for (int j = 0; j < 4; j++) split3(f[j], a0[j], a1[j], a2[j]);
            ull p0 = (ull)a0[0] | ((ull)a0[1] << 16) | ((ull)a0[2] << 32) | ((ull)a0[3] << 48);
            ull p1 = (ull)a1[0] | ((ull)a1[1] << 16) | ((ull)a1[2] << 32) | ((ull)a1[3] << 48);
            ull p2 = (ull)a2[0] | ((ull)a2[1] << 16) | ((ull)a2[2] << 32) | ((ull)a2[3] << 48);
            char* base = sm + SM_A + row * STRB + dq * 2;
            // TA = {0,0,1,1,0,2}: x0 -> segs 0,1,4; x1 -> segs 2,3; x2 -> seg 5
            *(ull*)(base + 0 * 128) = p0;
            *(ull*)(base + 1 * 128) = p0;
            *(ull*)(base + 4 * 128) = p0;
            *(ull*)(base + 2 * 128) = p1;
            *(ull*)(base + 3 * 128) = p1;
            *(ull*)(base + 5 * 128) = p2;
        }
        __syncthreads();

        float acc[8][4];
        #pragma unroll
        for (int n = 0; n < 8; n++)
            #pragma unroll
            for (int j = 0; j < 4; j++) acc[n][j] = 0.0f;

        #pragma unroll 6
        for (int kk = 0; kk < KE / 16; kk++) {       // 24 k-steps
            unsigned a[4];
            ldsm_x4(a[0], a[1], a[2], a[3], aAddrBase + kk * 32);
            #pragma unroll
            for (int p = 0; p < 4; p++) {            // 4 pairs of n-tiles (16 codes)
                unsigned b0, b1, b2, b3;
                unsigned bAddr = smb + SM_B + (cLoc + p * 16 + (l & 15)) * STRB
                               + kk * 32 + (l >> 4) * 16;
                ldsm_x4(b0, b1, b2, b3, bAddr);
                mma16816(acc[2 * p + 0], a, b0, b2);
                mma16816(acc[2 * p + 1], a, b1, b3);
            }
        }

        // --- scores + per-row argmin ---
        // d-frag: regs {0,1}: row l/4, cols (l%4)*2,+1; regs {2,3}: row l/4+8
        ull blo = ~0ull, bhi = ~0ull;
        #pragma unroll
        for (int n = 0; n < 8; n++) {
            int lc = cLoc + n * 8 + (l & 3) * 2;     // local code idx
            float e0 = esq_s[lc], e1 = esq_s[lc + 1];
            unsigned gc = qbase + lc;
            blo = umin64(blo, keyf(fmaf(-2.0f, acc[n][0], e0), gc));
            blo = umin64(blo, keyf(fmaf(-2.0f, acc[n][1], e1), gc + 1));
            bhi = umin64(bhi, keyf(fmaf(-2.0f, acc[n][2], e0), gc));
            bhi = umin64(bhi, keyf(fmaf(-2.0f, acc[n][3], e1), gc + 1));
        }
        // reduce over the 4 lanes of each quad (same rows, different cols)
        #pragma unroll
        for (int off = 1; off <= 2; off <<= 1) {
            blo = umin64(blo, __shfl_xor_sync(0xffffffffu, blo, off));
            bhi = umin64(bhi, __shfl_xor_sync(0xffffffffu, bhi, off));
        }
        if ((l & 3) == 0) {
            int r0 = tile * ROWT + aRow + (l >> 2);
            atomicMax(&g_best[r0],     ~blo);
            atomicMax(&g_best[r0 + 8], ~bhi);
        }
        __syncthreads();
    }
}

// ---------- winners -> idx, quantized, loss, cs/dw ----------
__global__ void __launch_bounds__(256) k_finish(
    const float* __restrict__ x, float* __restrict__ out)
{
    int r = blockIdx.x * 256 + threadIdx.x;
    ull keyi = g_best[r];
    g_best[r] = 0ull;                            // restore scratch
    unsigned bi = (unsigned)(~keyi) & 0xffffffffu;

    out[OFF_IDX + r] = (float)bi;
    atomicAdd(&g_cs[bi], 1.0f);

    const float4* xv = (const float4*)(x + (size_t)r * DD);
    const float4* ev = g_eTv + (size_t)bi * 16;
    float4* qv = (float4*)(out + OFF_Q + (size_t)r * DD);

    float lacc = 0.0f;
    #pragma unroll
    for (int i = 0; i < DD / 4; i++) {
        float4 xq = xv[i];
        float4 eq = ev[i];
        qv[i] = eq;
        float e0 = eq.x - xq.x, e1 = eq.y - xq.y;
        float e2 = eq.z - xq.z, e3 = eq.w - xq.w;
        lacc = fmaf(e0, e0, lacc); lacc = fmaf(e1, e1, lacc);
        lacc = fmaf(e2, e2, lacc); lacc = fmaf(e3, e3, lacc);
        atomicAdd(&g_dw[(4 * i + 0) * KK + bi], xq.x);
        atomicAdd(&g_dw[(4 * i + 1) * KK + bi], xq.y);
        atomicAdd(&g_dw[(4 * i + 2) * KK + bi], xq.z);
        atomicAdd(&g_dw[(4 * i + 3) * KK + bi], xq.w);
    }
    #pragma unroll
    for (int off = 16; off; off >>= 1)
        lacc += __shfl_down_sync(0xffffffffu, lacc, off);
    if ((threadIdx.x & 31) == 0) atomicAdd(&g_loss, lacc);
}

// ---------- per-code stats ----------
__global__ void k_fin1(const float* __restrict__ ema_cs,
                       const int* __restrict__ counter,
                       float* __restrict__ out)
{
    __shared__ double s_red[512];
    int t = threadIdx.x;

    double debias = 1.0 - pow(0.99, (double)(counter[0] + 1));

    float cs  = g_cs[t];
    g_cs[t] = 0.0f;
    float hid = ema_cs[t] * DECAYF + cs * (1.0f - DECAYF);
    out[OFF_HIDCS + t] = hid;
    float upd = (float)((double)hid / debias);

    s_red[t] = (double)upd;
    __syncthreads();
    for (int s = 256; s > 0; s >>= 1) {
        if (t < s) s_red[t] += s_red[t + s];
        __syncthreads();
    }
    double nsum = s_red[0];
    __syncthreads();

    double stable = (((double)upd + (double)EPSF)
                     / (nsum + (double)KK * (double)EPSF)) * nsum;
    g_inv_stable[t] = (float)(1.0 / stable);

    double p = (double)cs / (double)NV;
    s_red[t] = -p * log(p + 1e-10);
    __syncthreads();
    for (int s = 256; s > 0; s >>= 1) {
        if (t < s) s_red[t] += s_red[t + s];
        __syncthreads();
    }
    double ent = s_red[0];

    if (t == 0) {
        out[OFF_PERP] = (float)exp(ent);
        out[OFF_LOSS] = 0.25f * (g_loss / (float)(NV * DD));
        g_loss = 0.0f;
        g_inv_debias = (float)(1.0 / debias);
    }
}

// ---------- dw EMA map ----------
__global__ void k_fin2(const float* __restrict__ ema_dw,
                       float* __restrict__ out)
{
    int i = blockIdx.x * blockDim.x + threadIdx.x;   // 32768
    float inv_deb = g_inv_debias;
    float dwv = g_dw[i];
    g_dw[i] = 0.0f;
    float hdw = ema_dw[i] * DECAYF + dwv * (1.0f - DECAYF);
    out[OFF_HIDDW + i] = hdw;
    out[OFF_NEWEMB + i] = (hdw * inv_deb) * g_inv_stable[i & (KK - 1)];
}

extern "C" void kernel_launch(void* const* d_in, const int* in_sizes, int n_in,
                              void* d_out, int out_size)
{
    const float* x       = (const float*)d_in[0];
    const float* emb     = (const float*)d_in[1];
    const float* ema_cs  = (const float*)d_in[2];
    const float* ema_dw  = (const float*)d_in[3];
    const int*   counter = (const int*)d_in[4];
    float* out = (float*)d_out;

    cudaFuncSetAttribute(k_mma, cudaFuncAttributeMaxDynamicSharedMemorySize, SMEMM);

    k_prep_e<<<64, 512>>>(emb);
    k_mma<<<GRIDM, TPB, SMEMM>>>(x, emb);
    k_finish<<<NV / 256, 256>>>(x, out);
    k_fin1<<<1, KK>>>(ema_cs, counter, out);
    k_fin2<<<64, 512>>>(ema_dw, out);
}

// round 14
// speedup vs baseline: 1.3290x; 1.3290x over previous
#include <cuda_runtime.h>
#include <math.h>

#define DD 64
#define KK 512
#define NV 65536
#define DECAYF 0.99f
#define EPSF 1e-5f

#define TPB   384
#define NW    12            // warps
#define ROWT  96            // 12 warps x 8 rows
#define XS    100           // x-tile row stride (floats)
#define NT    683           // ceil(65536/96); last tile has 64 valid rows
#define GRID  152

// Output layout (concatenated float32, reference tuple order)
#define OFF_Q      0
#define OFF_LOSS   (NV * DD)
#define OFF_PERP   (OFF_LOSS + 1)
#define OFF_IDX    (OFF_PERP + 1)
#define OFF_NEWEMB (OFF_IDX + NV)
#define OFF_HIDCS  (OFF_NEWEMB + DD*KK)
#define OFF_HIDDW  (OFF_HIDCS + KK)

typedef unsigned long long ull;

// Packed fp32x2 FMA: 2 IEEE fp32 FMAs per instruction, bit-exact vs scalar fmaf.
__device__ __forceinline__ ull ffma2(ull a, ull b, ull c) {
    ull d;
    asm("fma.rn.f32x2 %0, %1, %2, %3;" : "=l"(d) : "l"(a), "l"(b), "l"(c));
    return d;
}
__device__ __forceinline__ ull pack2(float lo, float hi) {
    ull r;
    asm("mov.b64 %0, {%1, %2};" : "=l"(r) : "f"(lo), "f"(hi));
    return r;
}
__device__ __forceinline__ float2 unpack2(ull v) {
    float2 f;
    asm("mov.b64 {%0, %1}, %2;" : "=f"(f.x), "=f"(f.y) : "l"(v));
    return f;
}
// Monotonic float->uint key; idx in low 32 bits => u64-min == (min score, min idx)
__device__ __forceinline__ ull keyf(float s, unsigned idx) {
    unsigned u = __float_as_uint(s);
    u = (u & 0x80000000u) ? ~u : (u | 0x80000000u);
    return ((ull)u << 32) | (ull)idx;
}
__device__ __forceinline__ ull umin64(ull a, ull b) { return a < b ? a : b; }

// Scratch (device globals; zero-init at load, fin kernels restore zeros)
__device__ float g_dw[DD * KK];
__device__ float g_cs[KK];
__device__ float g_loss;
__device__ float g_inv_stable[KK];
__device__ float g_inv_debias;

__global__ void __launch_bounds__(TPB, 1) k_main(
    const float* __restrict__ x, const float* __restrict__ emb,
    float* __restrict__ out)
{
    extern __shared__ float sm[];
    float* es    = sm;                      // [64][512] codebook
    float* esq   = sm + DD * KK;            // [512]
    float* xs    = esq + KK;                // [64][XS] x-tile, transposed
    int*   sbidx = (int*)(xs + DD * XS);    // [96]

    const int t = threadIdx.x;
    const int w = t >> 5;       // warp 0..11 -> rows 8w..8w+7
    const int l = t & 31;       // lane -> code quads 4l, 128+4l (per half)

    // Stage codebook once (persistent blocks)
    {
        const float4* src = (const float4*)emb;
        float4* dst = (float4*)es;
        for (int i = t; i < DD * KK / 4; i += TPB) dst[i] = src[i];
    }
    __syncthreads();
    for (int k = t; k < KK; k += TPB) {
        float s = 0.0f;
        #pragma unroll
        for (int d = 0; d < DD; d++) {
            float v = es[d * KK + k];
            s = fmaf(v, v, s);
        }
        esq[k] = s;
    }
    __syncthreads();

    const ull M2 = pack2(-2.0f, -2.0f);
    float lacc = 0.0f;

    for (int tile = blockIdx.x; tile < NT; tile += gridDim.x) {
        const int rbase = tile * ROWT;
        // --- load x-tile transposed: xs[d][row] (1536 float4 tasks) ---
        #pragma unroll
        for (int i = 0; i < 4; i++) {
            int c   = t + TPB * i;
            int row = c >> 4;
            int dq  = (c & 15) * 4;
            if (rbase + row < NV) {
                float4 v = *(const float4*)(x + (size_t)(rbase + row) * DD + dq);
                xs[(dq + 0) * XS + row] = v.x;
                xs[(dq + 1) * XS + row] = v.y;
                xs[(dq + 2) * XS + row] = v.z;
                xs[(dq + 3) * XS + row] = v.w;
            }
        }
        __syncthreads();

        ull best[8];
        #pragma unroll
        for (int r = 0; r < 8; r++) best[r] = ~0ull;

        #pragma unroll
        for (int h = 0; h < 2; h++) {
            const int cb = 256 * h;
            ull acc[8][4];
            #pragma unroll
            for (int r = 0; r < 8; r++)
                #pragma unroll
                for (int j = 0; j < 4; j++) acc[r][j] = 0ull;

            #pragma unroll 2
            for (int d = 0; d < DD; d++) {
                // broadcast: all lanes read this warp's 8 rows at dim d
                float4 a0 = *(const float4*)(xs + d * XS + 8 * w);
                float4 a1 = *(const float4*)(xs + d * XS + 8 * w + 4);
                // conflict-free: lane l -> code quad 4l (and 128+4l)
                ulonglong2 b0 = *(const ulonglong2*)(es + d * KK + cb + 4 * l);
                ulonglong2 b1 = *(const ulonglong2*)(es + d * KK + cb + 128 + 4 * l);
                ull ax0 = pack2(a0.x, a0.x), ax1 = pack2(a0.y, a0.y);
                ull ax2 = pack2(a0.z, a0.z), ax3 = pack2(a0.w, a0.w);
                ull ax4 = pack2(a1.x, a1.x), ax5 = pack2(a1.y, a1.y);
                ull ax6 = pack2(a1.z, a1.z), ax7 = pack2(a1.w, a1.w);
                ull ax[8] = {ax0, ax1, ax2, ax3, ax4, ax5, ax6, ax7};
                #pragma unroll
                for (int r = 0; r < 8; r++) {
                    acc[r][0] = ffma2(ax[r], b0.x, acc[r][0]);
                    acc[r][1] = ffma2(ax[r], b0.y, acc[r][1]);
                    acc[r][2] = ffma2(ax[r], b1.x, acc[r][2]);
                    acc[r][3] = ffma2(ax[r], b1.y, acc[r][3]);
                }
            }
            // scores: s = ||e||^2 - 2 x.e  (||x||^2 const per row; argmin-safe)
            ulonglong2 eq0 = *(const ulonglong2*)(esq + cb + 4 * l);
            ulonglong2 eq1 = *(const ulonglong2*)(esq + cb + 128 + 4 * l);
            const unsigned c0 = cb + 4 * l, c1 = cb + 128 + 4 * l;
            #pragma unroll
            for (int r = 0; r < 8; r++) {
                float2 s0 = unpack2(ffma2(M2, acc[r][0], eq0.x));
                float2 s1 = unpack2(ffma2(M2, acc[r][1], eq0.y));
                float2 s2 = unpack2(ffma2(M2, acc[r][2], eq1.x));
                float2 s3 = unpack2(ffma2(M2, acc[r][3], eq1.y));
                best[r] = umin64(best[r], keyf(s0.x, c0 + 0));
                best[r] = umin64(best[r], keyf(s0.y, c0 + 1));
                best[r] = umin64(best[r], keyf(s1.x, c0 + 2));
                best[r] = umin64(best[r], keyf(s1.y, c0 + 3));
                best[r] = umin64(best[r], keyf(s2.x, c1 + 0));
                best[r] = umin64(best[r], keyf(s2.y, c1 + 1));
                best[r] = umin64(best[r], keyf(s3.x, c1 + 2));
                best[r] = umin64(best[r], keyf(s3.y, c1 + 3));
            }
        }

        // cross-lane argmin per row (u64 min keeps exact first-occurrence tie-break)
        #pragma unroll
        for (int r = 0; r < 8; r++) {
            #pragma unroll
            for (int off = 16; off; off >>= 1) {
                ull o = __shfl_xor_sync(0xffffffffu, best[r], off);
                best[r] = umin64(best[r], o);
            }
        }
        if (l == 0) {
            #pragma unroll
            for (int r = 0; r < 8; r++) {
                int row = 8 * w + r;
                if (rbase + row < NV) {
                    int bi = (int)(best[r] & 0xffffffffull);
                    sbidx[row] = bi;
                    out[OFF_IDX + rbase + row] = (float)bi;
                    atomicAdd(&g_cs[bi], 1.0f);
                }
            }
        }
        __syncthreads();

        // --- epilogue: quantized gather, loss, dw scatter (1536 tasks) ---
        #pragma unroll
        for (int i = 0; i < 4; i++) {
            int c   = t + TPB * i;
            int row = c % ROWT;
            int d4  = (c / ROWT) * 4;
            if (rbase + row < NV) {
                int bi = sbidx[row];
                float q0 = es[(d4 + 0) * KK + bi];
                float q1 = es[(d4 + 1) * KK + bi];
                float q2 = es[(d4 + 2) * KK + bi];
                float q3 = es[(d4 + 3) * KK + bi];
                float x0 = xs[(d4 + 0) * XS + row];
                float x1 = xs[(d4 + 1) * XS + row];
                float x2 = xs[(d4 + 2) * XS + row];
                float x3 = xs[(d4 + 3) * XS + row];
                float e0 = q0 - x0, e1 = q1 - x1, e2 = q2 - x2, e3 = q3 - x3;
                lacc = fmaf(e0, e0, lacc); lacc = fmaf(e1, e1, lacc);
                lacc = fmaf(e2, e2, lacc); lacc = fmaf(e3, e3, lacc);
                *(float4*)(out + OFF_Q + (size_t)(rbase + row) * DD + d4)
                    = make_float4(q0, q1, q2, q3);
                atomicAdd(&g_dw[(d4 + 0) * KK + bi], x0);
                atomicAdd(&g_dw[(d4 + 1) * KK + bi], x1);
                atomicAdd(&g_dw[(d4 + 2) * KK + bi], x2);
                atomicAdd(&g_dw[(d4 + 3) * KK + bi], x3);
            }
        }
        __syncthreads();
    }

    // loss: warp-reduce then one atomic per warp
    #pragma unroll
    for (int off = 16; off; off >>= 1)
        lacc += __shfl_down_sync(0xffffffffu, lacc, off);
    if (l == 0 && lacc != 0.0f) atomicAdd(&g_loss, lacc);
}

// --- epilogue part 1: per-code stats, fp32 fast path (1 block, 512 threads) ---
__global__ void k_fin1(const float* __restrict__ ema_cs,
                       const int* __restrict__ counter,
                       float* __restrict__ out)
{
    __shared__ float s_part[16];
    __shared__ float s_bcast[2];           // [0]=inv_debias, [1]=reduced scalar
    const int t = threadIdx.x;             // 512 == KK
    const int w = t >> 5, l = t & 31;

    if (t == 0) {
        double db = 1.0 - pow(0.99, (double)(counter[0] + 1));
        float invdb = (float)(1.0 / db);
        s_bcast[0] = invdb;
        g_inv_debias = invdb;
        out[OFF_LOSS] = 0.25f * (g_loss / (float)(NV * DD));
        g_loss = 0.0f;
    }
    __syncthreads();
    const float inv_db = s_bcast[0];

    float cs  = g_cs[t];
    g_cs[t] = 0.0f;                        // restore scratch
    float hid = ema_cs[t] * DECAYF + cs * (1.0f - DECAYF);
    out[OFF_HIDCS + t] = hid;
    float upd = hid * inv_db;

    // nsum = sum(upd) via shuffle + smem
    float v = upd;
    #pragma unroll
    for (int off = 16; off; off >>= 1) v += __shfl_xor_sync(0xffffffffu, v, off);
    if (l == 0) s_part[w] = v;
    __syncthreads();
    if (t < 32) {
        float pv = (t < 16) ? s_part[t] : 0.0f;
        #pragma unroll
        for (int off = 8; off; off >>= 1) pv += __shfl_xor_sync(0xffffffffu, pv, off);
        if (t == 0) s_bcast[1] = pv;
    }
    __syncthreads();
    const float nsum = s_bcast[1];

    float stable = ((upd + EPSF) / (nsum + (float)KK * EPSF)) * nsum;
    g_inv_stable[t] = 1.0f / stable;

    // entropy
    float p = cs * (1.0f / (float)NV);
    float e = -p * logf(p + 1e-10f);
    #pragma unroll
    for (int off = 16; off; off >>= 1) e += __shfl_xor_sync(0xffffffffu, e, off);
    if (l == 0) s_part[w] = e;
    __syncthreads();
    if (t < 32) {
        float pv = (t < 16) ? s_part[t] : 0.0f;
        #pragma unroll
        for (int off = 8; off; off >>= 1) pv += __shfl_xor_sync(0xffffffffu, pv, off);
        if (t == 0) out[OFF_PERP] = expf(pv);
    }
}

// --- epilogue part 2: 32K-element elementwise map, fp32 only, many blocks ---
__global__ void k_fin2(const float* __restrict__ ema_dw,
                       float* __restrict__ out)
{
    int i = blockIdx.x * blockDim.x + threadIdx.x;   // 64 x 512 = 32768
    float inv_deb = g_inv_debias;
    float dwv = g_dw[i];
    g_dw[i] = 0.0f;                       // restore scratch
    float hdw = ema_dw[i] * DECAYF + dwv * (1.0f - DECAYF);
    out[OFF_HIDDW + i] = hdw;
    out[OFF_NEWEMB + i] = (hdw * inv_deb) * g_inv_stable[i & (KK - 1)];
}

extern "C" void kernel_launch(void* const* d_in, const int* in_sizes, int n_in,
                              void* d_out, int out_size)
{
    const float* x       = (const float*)d_in[0];
    const float* emb     = (const float*)d_in[1];
    const float* ema_cs  = (const float*)d_in[2];
    const float* ema_dw  = (const float*)d_in[3];
    const int*   counter = (const int*)d_in[4];
    float* out = (float*)d_out;

    const int smem = (DD * KK + KK + DD * XS) * (int)sizeof(float)
                   + ROWT * (int)sizeof(int);        // 159,104 B
    cudaFuncSetAttribute(k_main, cudaFuncAttributeMaxDynamicSharedMemorySize, smem);

    k_main<<<GRID, TPB, smem>>>(x, emb, out);
    k_fin1<<<1, KK>>>(ema_cs, counter, out);
    k_fin2<<<64, 512>>>(ema_dw, out);
}